// round 8
// baseline (speedup 1.0000x reference)
#include <cuda_runtime.h>

#define TPB 128
typedef unsigned long long ull;

// MULT = pi - float-eps, folded into the stage-E quadratic form.
#define MULT_F (3.141592653589793 - 1.1920928955078125e-07)

// Precomputed (theta-dependent, batch-invariant):
//  g_Wf : stages A,B,C (12 circuits). float[c][k][0..15]=Re(W[k][col]),
//         [16..31]=Im(W[k][col]).  Row = 8 re-pair ulls + 8 im-pair ulls.
//  g_M  : quadratic forms, circuits 12..16 (D,E); E pre-scaled by MULT.
__device__ __align__(16) float g_Wf[12 * 512];
__device__ __align__(16) float g_M[5 * 256];

// theta slice per circuit: A->theta[0], B->theta[3], C->theta[4], D->theta[1], E->theta[2][0]
__device__ __forceinline__ int circ_slice(int c) {
    if (c < 4)  return c;
    if (c < 8)  return 12 + (c - 4);
    if (c < 12) return 16 + (c - 8);
    if (c < 16) return 4 + (c - 12);
    return 8;
}

// One block per circuit (16 threads = 16 basis columns).
__global__ void build_WM(const float* __restrict__ theta) {
    const int c = blockIdx.x, col = threadIdx.x;
    const float* w = theta + circ_slice(c) * 48;

    float sr[16], si[16];
#pragma unroll
    for (int i = 0; i < 16; i++) { sr[i] = (i == col) ? 1.f : 0.f; si[i] = 0.f; }
#pragma unroll
    for (int l = 0; l < 4; l++) {
#pragma unroll
        for (int q = 0; q < 4; q++) {
            const float phi = w[(l * 4 + q) * 3 + 0];
            const float th  = w[(l * 4 + q) * 3 + 1];
            const float om  = w[(l * 4 + q) * 3 + 2];
            float ch, sh, ca, sa, cb, sb;
            __sincosf(0.5f * th, &sh, &ch);
            __sincosf(0.5f * (phi + om), &sa, &ca);
            __sincosf(0.5f * (phi - om), &sb, &cb);
            const float u00r =  ca * ch, u00i = -sa * ch;
            const float u01r = -cb * sh, u01i = -sb * sh;
            const float u10r =  cb * sh, u10i = -sb * sh;
            const float u11r =  ca * ch, u11i =  sa * ch;
            const int mask = 8 >> q;
#pragma unroll
            for (int k = 0; k < 16; k++) {
                if (k & mask) continue;
                const int k1 = k | mask;
                float ar = sr[k],  ai = si[k];
                float br = sr[k1], bi = si[k1];
                sr[k]  = u00r * ar - u00i * ai + u01r * br - u01i * bi;
                si[k]  = u00r * ai + u00i * ar + u01r * bi + u01i * br;
                sr[k1] = u10r * ar - u10i * ai + u11r * br - u11i * bi;
                si[k1] = u10r * ai + u10i * ar + u11r * bi + u11i * br;
            }
        }
        const int r = (l % 3) + 1;
#pragma unroll
        for (int q = 0; q < 4; q++) {
            const int cm = 8 >> q;
            const int tm = 8 >> ((q + r) & 3);
#pragma unroll
            for (int k = 0; k < 16; k++) {
                if ((k & cm) && !(k & tm)) {
                    const int k1 = k | tm;
                    float tr = sr[k], ti = si[k];
                    sr[k] = sr[k1]; si[k] = si[k1];
                    sr[k1] = tr;    si[k1] = ti;
                }
            }
        }
    }

    if (c < 12) {
#pragma unroll
        for (int k = 0; k < 16; k++) {
            g_Wf[c * 512 + k * 32 + col]      = sr[k];   // re
            g_Wf[c * 512 + k * 32 + 16 + col] = si[k];   // im
        }
    } else {
        __shared__ float2 sWt[256];
#pragma unroll
        for (int k = 0; k < 16; k++) sWt[k * 16 + col] = make_float2(sr[k], si[k]);
        __syncthreads();
        const int r = col;
        float m[16];
#pragma unroll
        for (int j = 0; j < 16; j++) m[j] = 0.f;
#pragma unroll
        for (int k = 0; k < 16; k++) {
            const float2 wr = sWt[k * 16 + r];
#pragma unroll
            for (int j = 0; j < 16; j++) {
                const float2 wj = sWt[k * 16 + j];
                const float tt = wr.x * wj.x + wr.y * wj.y;
                m[j] = (k & 8) ? (m[j] - tt) : (m[j] + tt);
            }
        }
        const float scale = (c == 16) ? (float)MULT_F : 1.f;
#pragma unroll
        for (int j = 0; j < 16; j++) g_M[(c - 12) * 256 + r * 16 + j] = m[j] * scale;
    }
}

// ---------------------------------------------------------------------------
// f32x2 packed helpers
// ---------------------------------------------------------------------------
__device__ __forceinline__ ull pk2(float lo, float hi) {
    ull r; asm("mov.b64 %0, {%1, %2};" : "=l"(r) : "f"(lo), "f"(hi)); return r;
}
__device__ __forceinline__ void unpk2(ull v, float& lo, float& hi) {
    asm("mov.b64 {%0, %1}, %2;" : "=f"(lo), "=f"(hi) : "l"(v));
}
__device__ __forceinline__ ull ffma2(ull a, ull b, ull c) {
    ull d; asm("fma.rn.f32x2 %0, %1, %2, %3;" : "=l"(d) : "l"(a), "l"(b), "l"(c)); return d;
}
__device__ __forceinline__ ull fmul2(ull a, ull b) {
    ull d; asm("mul.rn.f32x2 %0, %1, %2;" : "=l"(d) : "l"(a), "l"(b)); return d;
}
__device__ __forceinline__ ull fadd2(ull a, ull b) {
    ull d; asm("add.rn.f32x2 %0, %1, %2;" : "=l"(d) : "l"(a), "l"(b)); return d;
}

// psi (j-pair packed) from 4 angles: pj[i*2]   = (u_i v0, u_i v1)
//                                    pj[i*2+1] = (u_i v2, u_i v3)
__device__ __forceinline__ void emb_pj(const float* a, ull* pj) {
    float s0, c0, s1, c1, s2, c2, s3, c3;
    __sincosf(0.5f * a[0], &s0, &c0);
    __sincosf(0.5f * a[1], &s1, &c1);
    __sincosf(0.5f * a[2], &s2, &c2);
    __sincosf(0.5f * a[3], &s3, &c3);
    const float u[4] = { c0 * c1, c0 * s1, s0 * c1, s0 * s1 };
    const float v[4] = { c2 * c3, c2 * s3, s2 * c3, s2 * s3 };
#pragma unroll
    for (int i = 0; i < 4; i++) {
        pj[i * 2 + 0] = pk2(u[i] * v[0], u[i] * v[1]);
        pj[i * 2 + 1] = pk2(u[i] * v[2], u[i] * v[3]);
    }
}

// Dual-element full circuit: 4 expvals each. W = re/im split, j-pair layout.
__device__ __forceinline__ void run4x2(const ull* __restrict__ W,
                                       const float* aA, const float* aB,
                                       float* oA, float* oB) {
    ull pjA[8], pjB[8];
    emb_pj(aA, pjA);
    emb_pj(aB, pjB);
    float eA[4] = {0.f, 0.f, 0.f, 0.f}, eB[4] = {0.f, 0.f, 0.f, 0.f};
#pragma unroll 4
    for (int k = 0; k < 16; k++) {
        const ulonglong2* R = (const ulonglong2*)(W + k * 16);
        const ulonglong2 r0 = R[0], r1 = R[1], r2 = R[2], r3 = R[3]; // re pairs
        const ulonglong2 i0 = R[4], i1 = R[5], i2 = R[6], i3 = R[7]; // im pairs
        // element A
        ull ra0 = fmul2(r0.x, pjA[0]), ra1 = fmul2(r0.y, pjA[1]);
        ra0 = ffma2(r1.x, pjA[2], ra0); ra1 = ffma2(r1.y, pjA[3], ra1);
        ra0 = ffma2(r2.x, pjA[4], ra0); ra1 = ffma2(r2.y, pjA[5], ra1);
        ra0 = ffma2(r3.x, pjA[6], ra0); ra1 = ffma2(r3.y, pjA[7], ra1);
        ull ia0 = fmul2(i0.x, pjA[0]), ia1 = fmul2(i0.y, pjA[1]);
        ia0 = ffma2(i1.x, pjA[2], ia0); ia1 = ffma2(i1.y, pjA[3], ia1);
        ia0 = ffma2(i2.x, pjA[4], ia0); ia1 = ffma2(i2.y, pjA[5], ia1);
        ia0 = ffma2(i3.x, pjA[6], ia0); ia1 = ffma2(i3.y, pjA[7], ia1);
        // element B
        ull rb0 = fmul2(r0.x, pjB[0]), rb1 = fmul2(r0.y, pjB[1]);
        rb0 = ffma2(r1.x, pjB[2], rb0); rb1 = ffma2(r1.y, pjB[3], rb1);
        rb0 = ffma2(r2.x, pjB[4], rb0); rb1 = ffma2(r2.y, pjB[5], rb1);
        rb0 = ffma2(r3.x, pjB[6], rb0); rb1 = ffma2(r3.y, pjB[7], rb1);
        ull ib0 = fmul2(i0.x, pjB[0]), ib1 = fmul2(i0.y, pjB[1]);
        ib0 = ffma2(i1.x, pjB[2], ib0); ib1 = ffma2(i1.y, pjB[3], ib1);
        ib0 = ffma2(i2.x, pjB[4], ib0); ib1 = ffma2(i2.y, pjB[5], ib1);
        ib0 = ffma2(i3.x, pjB[6], ib0); ib1 = ffma2(i3.y, pjB[7], ib1);

        float lo, hi;
        unpk2(fadd2(ra0, ra1), lo, hi); const float yrA = lo + hi;
        unpk2(fadd2(ia0, ia1), lo, hi); const float yiA = lo + hi;
        unpk2(fadd2(rb0, rb1), lo, hi); const float yrB = lo + hi;
        unpk2(fadd2(ib0, ib1), lo, hi); const float yiB = lo + hi;
        const float pA = fmaf(yrA, yrA, yiA * yiA);
        const float pB = fmaf(yrB, yrB, yiB * yiB);
        eA[0] = (k & 8) ? (eA[0] - pA) : (eA[0] + pA);
        eA[1] = (k & 4) ? (eA[1] - pA) : (eA[1] + pA);
        eA[2] = (k & 2) ? (eA[2] - pA) : (eA[2] + pA);
        eA[3] = (k & 1) ? (eA[3] - pA) : (eA[3] + pA);
        eB[0] = (k & 8) ? (eB[0] - pB) : (eB[0] + pB);
        eB[1] = (k & 4) ? (eB[1] - pB) : (eB[1] + pB);
        eB[2] = (k & 2) ? (eB[2] - pB) : (eB[2] + pB);
        eB[3] = (k & 1) ? (eB[3] - pB) : (eB[3] + pB);
    }
#pragma unroll
    for (int i = 0; i < 4; i++) { oA[i] = eA[i]; oB[i] = eB[i]; }
}

// Dual-element single expval via real quadratic form e = psi^T M psi.
__device__ __forceinline__ void run1x2(const float* __restrict__ M,
                                       const float* aA, const float* aB,
                                       float& rA, float& rB) {
    float psiA[16], psiB[16];
    {
        float s0, c0, s1, c1, s2, c2, s3, c3;
        __sincosf(0.5f * aA[0], &s0, &c0);
        __sincosf(0.5f * aA[1], &s1, &c1);
        __sincosf(0.5f * aA[2], &s2, &c2);
        __sincosf(0.5f * aA[3], &s3, &c3);
        const float u[4] = { c0 * c1, c0 * s1, s0 * c1, s0 * s1 };
        const float v[4] = { c2 * c3, c2 * s3, s2 * c3, s2 * s3 };
#pragma unroll
        for (int i = 0; i < 4; i++)
#pragma unroll
            for (int j = 0; j < 4; j++) psiA[i * 4 + j] = u[i] * v[j];
    }
    {
        float s0, c0, s1, c1, s2, c2, s3, c3;
        __sincosf(0.5f * aB[0], &s0, &c0);
        __sincosf(0.5f * aB[1], &s1, &c1);
        __sincosf(0.5f * aB[2], &s2, &c2);
        __sincosf(0.5f * aB[3], &s3, &c3);
        const float u[4] = { c0 * c1, c0 * s1, s0 * c1, s0 * s1 };
        const float v[4] = { c2 * c3, c2 * s3, s2 * c3, s2 * s3 };
#pragma unroll
        for (int i = 0; i < 4; i++)
#pragma unroll
            for (int j = 0; j < 4; j++) psiB[i * 4 + j] = u[i] * v[j];
    }
    ull pjA[8], pjB[8];
#pragma unroll
    for (int j = 0; j < 8; j++) {
        pjA[j] = pk2(psiA[2 * j], psiA[2 * j + 1]);
        pjB[j] = pk2(psiB[2 * j], psiB[2 * j + 1]);
    }
    float eA0 = 0.f, eA1 = 0.f, eB0 = 0.f, eB1 = 0.f;
#pragma unroll 4
    for (int k = 0; k < 16; k++) {
        const ulonglong2* row = (const ulonglong2*)(M + k * 16);
        const ulonglong2 m0 = row[0], m1 = row[1], m2 = row[2], m3 = row[3];
        ull a0 = fmul2(m0.x, pjA[0]), a1 = fmul2(m0.y, pjA[1]);
        a0 = ffma2(m1.x, pjA[2], a0); a1 = ffma2(m1.y, pjA[3], a1);
        a0 = ffma2(m2.x, pjA[4], a0); a1 = ffma2(m2.y, pjA[5], a1);
        a0 = ffma2(m3.x, pjA[6], a0); a1 = ffma2(m3.y, pjA[7], a1);
        ull b0 = fmul2(m0.x, pjB[0]), b1 = fmul2(m0.y, pjB[1]);
        b0 = ffma2(m1.x, pjB[2], b0); b1 = ffma2(m1.y, pjB[3], b1);
        b0 = ffma2(m2.x, pjB[4], b0); b1 = ffma2(m2.y, pjB[5], b1);
        b0 = ffma2(m3.x, pjB[6], b0); b1 = ffma2(m3.y, pjB[7], b1);
        float lo, hi;
        unpk2(fadd2(a0, a1), lo, hi);
        if (k & 1) eA1 = fmaf(psiA[k], lo + hi, eA1);
        else       eA0 = fmaf(psiA[k], lo + hi, eA0);
        unpk2(fadd2(b0, b1), lo, hi);
        if (k & 1) eB1 = fmaf(psiB[k], lo + hi, eB1);
        else       eB0 = fmaf(psiB[k], lo + hi, eB0);
    }
    rA = eA0 + eA1;
    rB = eB0 + eB1;
}

// ---------------------------------------------------------------------------
// Main kernel: block = 64-element tile; warp w = circuit w per stage;
// each thread handles 2 elements (lane, lane+32). Broadcast W reads.
// ---------------------------------------------------------------------------
__global__ __launch_bounds__(TPB, 4)
void vqc_warp2(const float* __restrict__ x, float* __restrict__ out, int B) {
    __shared__ __align__(16) ull   sW[12 * 256];   // 24 KB
    __shared__ __align__(16) float sM[5 * 256];    // 5 KB
    __shared__ float sH[64][17];                   // 4.25 KB

    const int tid = threadIdx.x;
    {
        const float4* s1 = (const float4*)g_Wf;
        float4* d1 = (float4*)sW;
        for (int i = tid; i < 1536; i += TPB) d1[i] = s1[i];
        const float4* s2 = (const float4*)g_M;
        float4* d2 = (float4*)sM;
        for (int i = tid; i < 320; i += TPB) d2[i] = s2[i];
    }

    const int e0 = blockIdx.x * 64;
    for (int i = tid; i < 64 * 13; i += TPB) {
        const long gi = (long)e0 * 13 + i;
        if (gi < (long)B * 13) sH[i / 13][i % 13] = x[gi];
    }
    __syncthreads();

    const int w  = tid >> 5;
    const int eA = tid & 31, eB = eA + 32;
    float aA[4], aB[4], oA[4], oB[4];

    // Stage A inputs: H = [0, x0..x12, 0, 0]; circuit w uses H[4w..4w+3]
#pragma unroll
    for (int i = 0; i < 4; i++) {
        const int j = 4 * w + i;
        const bool in = (j >= 1 && j <= 13);
        aA[i] = in ? sH[eA][j - 1] : 0.f;
        aB[i] = in ? sH[eB][j - 1] : 0.f;
    }
    __syncthreads();

    // Stage A
    run4x2(sW + w * 256, aA, aB, oA, oB);
#pragma unroll
    for (int i = 0; i < 4; i++) { sH[eA][4 * w + i] = oA[i]; sH[eB][4 * w + i] = oB[i]; }
    __syncthreads();

    // Stages B, C share one code instantiation (identical transposed wiring)
    for (int s = 1; s <= 2; s++) {
#pragma unroll
        for (int i = 0; i < 4; i++) { aA[i] = sH[eA][4 * i + w]; aB[i] = sH[eB][4 * i + w]; }
        __syncthreads();
        run4x2(sW + (4 * s + w) * 256, aA, aB, oA, oB);
#pragma unroll
        for (int i = 0; i < 4; i++) { sH[eA][4 * w + i] = oA[i]; sH[eB][4 * w + i] = oB[i]; }
        __syncthreads();
    }

    // Stage D inputs (transposed), then quadratic form w
#pragma unroll
    for (int i = 0; i < 4; i++) { aA[i] = sH[eA][4 * i + w]; aB[i] = sH[eB][4 * i + w]; }
    __syncthreads();
    float hA, hB;
    run1x2(sM + w * 256, aA, aB, hA, hB);
    sH[eA][w] = hA; sH[eB][w] = hB;
    __syncthreads();

    // Stage E: warp 0 only (MULT baked into sM[4])
    if (w != 0) return;
#pragma unroll
    for (int i = 0; i < 4; i++) { aA[i] = sH[eA][i]; aB[i] = sH[eB][i]; }
    float rA, rB;
    run1x2(sM + 4 * 256, aA, aB, rA, rB);
    if (e0 + eA < B) out[e0 + eA] = rA;
    if (e0 + eB < B) out[e0 + eB] = rB;
}

extern "C" void kernel_launch(void* const* d_in, const int* in_sizes, int n_in,
                              void* d_out, int out_size) {
    const float* x     = (const float*)d_in[0];
    const float* theta = (const float*)d_in[1];
    if (n_in >= 2 && in_sizes[0] < in_sizes[1]) {
        x     = (const float*)d_in[1];
        theta = (const float*)d_in[0];
    }
    float* out = (float*)d_out;
    const int B = out_size;

    build_WM<<<17, 16>>>(theta);
    vqc_warp2<<<(B + 63) / 64, TPB>>>(x, out, B);
}